// round 6
// baseline (speedup 1.0000x reference)
#include <cuda_runtime.h>
#include <cstddef>

#define NTOK   196
#define DMODEL 384
#define NHEADS 16
#define HDIM   6144
#define NBATCH 4
#define NROWS  784          // NBATCH * NTOK
#define NBC    1536         // NBATCH * DMODEL
#define SPLITK 8

// ---------------- scratch (static __device__, no allocation) ----------------
__device__ float g_xn[NROWS * DMODEL];                         // 1.2 MB
// qkv layout: [b][c][h][i]  (per (b,c): 16*196 contiguous floats)
__device__ float g_q[(size_t)NBC * NHEADS * NTOK];             // 19.3 MB
__device__ float g_k[(size_t)NBC * NHEADS * NTOK];
__device__ float g_v[(size_t)NBC * NHEADS * NTOK];
// attn out layout: [row][ c*16 + h ]  (K-permuted for dense 64B writes)
__device__ float g_attn[(size_t)NROWS * HDIM];                 // 19.3 MB
__device__ float g_part[SPLITK][NROWS * DMODEL];               // 9.6 MB

// ---------------- packed f32x2 helpers (sm_100+; ptxas never emits FFMA2 from C++) ----
__device__ __forceinline__ unsigned long long pack2(float lo, float hi) {
    unsigned long long r;
    asm("mov.b64 %0, {%1, %2};" : "=l"(r) : "f"(lo), "f"(hi));
    return r;
}
__device__ __forceinline__ void fma2(unsigned long long& d,
                                     unsigned long long a, unsigned long long b) {
    asm("fma.rn.f32x2 %0, %1, %2, %0;" : "+l"(d) : "l"(a), "l"(b));
}
__device__ __forceinline__ unsigned long long add2(unsigned long long a,
                                                   unsigned long long b) {
    unsigned long long r;
    asm("add.rn.f32x2 %0, %1, %2;" : "=l"(r) : "l"(a), "l"(b));
    return r;
}
__device__ __forceinline__ void unpack2(unsigned long long v, float& lo, float& hi) {
    asm("mov.b64 {%0, %1}, %2;" : "=f"(lo), "=f"(hi) : "l"(v));
}

// ---------------- LayerNorm ----------------
__global__ void ln_kernel(const float* __restrict__ x,
                          const float* __restrict__ gamma,
                          const float* __restrict__ beta) {
    int row = blockIdx.x;
    int tid = threadIdx.x;                 // 128 threads
    const float* xr = x + (size_t)row * DMODEL;

    float v[3];
    float s = 0.f, s2 = 0.f;
#pragma unroll
    for (int t = 0; t < 3; t++) {
        float val = xr[tid + t * 128];
        v[t] = val;
        s  += val;
        s2 += val * val;
    }
#pragma unroll
    for (int off = 16; off; off >>= 1) {
        s  += __shfl_xor_sync(0xffffffffu, s,  off);
        s2 += __shfl_xor_sync(0xffffffffu, s2, off);
    }
    __shared__ float red[2][4];
    int wid = tid >> 5, lane = tid & 31;
    if (lane == 0) { red[0][wid] = s; red[1][wid] = s2; }
    __syncthreads();
    s  = red[0][0] + red[0][1] + red[0][2] + red[0][3];
    s2 = red[1][0] + red[1][1] + red[1][2] + red[1][3];

    float mu  = s * (1.f / DMODEL);
    float var = s2 * (1.f / DMODEL) - mu * mu;
    float inv = rsqrtf(var + 1e-5f);
#pragma unroll
    for (int t = 0; t < 3; t++) {
        int c = tid + t * 128;
        g_xn[(size_t)row * DMODEL + c] = (v[t] - mu) * inv * gamma[c] + beta[c];
    }
}

// ---------------- Fused projection GEMM: xn(784x384) @ W(384x6144), z selects Wq/Wk/Wv ----
// BM=BN=128, BK=8, 256 threads, 8x8 microtile (packed f32x2), double-buffered smem.
// Output: [b][c][h][i] — dense float4 stores per output column.
__global__ __launch_bounds__(256) void proj_gemm(const float* __restrict__ Wq,
                                                 const float* __restrict__ Wk,
                                                 const float* __restrict__ Wv) {
    int which = blockIdx.z;
    const float* W = (which == 0) ? Wq : (which == 1) ? Wk : Wv;
    float* outp    = (which == 0) ? g_q : (which == 1) ? g_k : g_v;

    __shared__ float As[2][8][128];
    __shared__ float Bs[2][8][128];

    int n0 = blockIdx.x * 128;
    int m0 = blockIdx.y * 128;
    int tid = threadIdx.x;
    int tx = tid & 15;        // row group
    int ty = tid >> 4;        // col group

    int ar   = tid >> 1;            // 0..127
    int ak   = (tid & 1) * 4;       // 0 or 4
    int arow = m0 + ar;
    int br   = tid >> 5;            // 0..7
    int bc4  = (tid & 31) * 4;      // 0..124

    unsigned long long acc2[8][4] = {};   // (0.f,0.f) == 0ull

    {   // prologue: tile 0
        float4 av = (arow < NROWS)
            ? *reinterpret_cast<const float4*>(&g_xn[(size_t)arow * DMODEL + ak])
            : make_float4(0.f, 0.f, 0.f, 0.f);
        float4 bv = *reinterpret_cast<const float4*>(&W[(size_t)br * HDIM + n0 + bc4]);
        As[0][ak + 0][ar] = av.x;
        As[0][ak + 1][ar] = av.y;
        As[0][ak + 2][ar] = av.z;
        As[0][ak + 3][ar] = av.w;
        *reinterpret_cast<float4*>(&Bs[0][br][bc4]) = bv;
    }
    __syncthreads();

    int buf = 0;
    for (int kt = 8; kt <= DMODEL; kt += 8) {
        float4 av, bv;
        bool more = (kt < DMODEL);
        if (more) {
            av = (arow < NROWS)
                ? *reinterpret_cast<const float4*>(&g_xn[(size_t)arow * DMODEL + kt + ak])
                : make_float4(0.f, 0.f, 0.f, 0.f);
            bv = *reinterpret_cast<const float4*>(&W[(size_t)(kt + br) * HDIM + n0 + bc4]);
        }
#pragma unroll
        for (int k = 0; k < 8; k++) {
            float4 a0 = *reinterpret_cast<const float4*>(&As[buf][k][tx * 8]);
            float4 a1 = *reinterpret_cast<const float4*>(&As[buf][k][tx * 8 + 4]);
            // B pairs read directly as 64-bit operands (32B-aligned smem)
            ulonglong2 bq0 = *reinterpret_cast<const ulonglong2*>(&Bs[buf][k][ty * 8]);
            ulonglong2 bq1 = *reinterpret_cast<const ulonglong2*>(&Bs[buf][k][ty * 8 + 4]);
            float a[8] = {a0.x, a0.y, a0.z, a0.w, a1.x, a1.y, a1.z, a1.w};
#pragma unroll
            for (int i = 0; i < 8; i++) {
                unsigned long long ap = pack2(a[i], a[i]);
                fma2(acc2[i][0], ap, bq0.x);
                fma2(acc2[i][1], ap, bq0.y);
                fma2(acc2[i][2], ap, bq1.x);
                fma2(acc2[i][3], ap, bq1.y);
            }
        }
        if (more) {
            int nb = buf ^ 1;
            As[nb][ak + 0][ar] = av.x;
            As[nb][ak + 1][ar] = av.y;
            As[nb][ak + 2][ar] = av.z;
            As[nb][ak + 3][ar] = av.w;
            *reinterpret_cast<float4*>(&Bs[nb][br][bc4]) = bv;
            __syncthreads();
            buf = nb;
        }
    }

    // unpack accumulators
    float acc[8][8];
#pragma unroll
    for (int i = 0; i < 8; i++)
#pragma unroll
        for (int jj = 0; jj < 4; jj++)
            unpack2(acc2[i][jj], acc[i][2 * jj], acc[i][2 * jj + 1]);

    // epilogue: col j_glob = n0 + ty*8 + j lies in one h (384 = 3*128 tiles).
    // address = ((b*DMODEL + c)*NHEADS + h)*NTOK + i
    int h  = n0 / DMODEL;
    int cb = n0 - h * DMODEL + ty * 8;
    int rbase = m0 + tx * 8;
    int bfirst = rbase / NTOK;
    int blast  = (rbase + 7) / NTOK;
    if (rbase + 7 < NROWS && bfirst == blast) {
        int ii0 = rbase - bfirst * NTOK;           // multiple of 4 -> float4 aligned
#pragma unroll
        for (int j = 0; j < 8; j++) {
            int c = cb + j;
            float* dst = &outp[((size_t)(bfirst * DMODEL + c) * NHEADS + h) * NTOK + ii0];
            *reinterpret_cast<float4*>(dst)     = make_float4(acc[0][j], acc[1][j], acc[2][j], acc[3][j]);
            *reinterpret_cast<float4*>(dst + 4) = make_float4(acc[4][j], acc[5][j], acc[6][j], acc[7][j]);
        }
    } else {
#pragma unroll
        for (int i = 0; i < 8; i++) {
            int row = rbase + i;
            if (row < NROWS) {
                int b  = row / NTOK;
                int ii = row - b * NTOK;
#pragma unroll
                for (int j = 0; j < 8; j++) {
                    int c = cb + j;
                    outp[((size_t)(b * DMODEL + c) * NHEADS + h) * NTOK + ii] = acc[i][j];
                }
            }
        }
    }
}

// ---------------- Channel attention: one block per (b,c), packed f32x2 math ----------------
__global__ __launch_bounds__(256) void attn_kernel(float* __restrict__ probs) {
    int bc = blockIdx.x;                   // b*384 + c
    __shared__ float Qs[NTOK][16];
    __shared__ float Ks[NTOK][20];         // 80B row stride: 16B-aligned, LDS.128 conflict-free
    __shared__ float Vs[NTOK][20];

    int tid = threadIdx.x;
    size_t qb = (size_t)bc * (NTOK * NHEADS);
    // memory layout [h][i]; smem layout [i][h]. Global reads stay contiguous.
    for (int idx = tid; idx < NTOK * NHEADS; idx += 256) {
        int h = idx / NTOK;
        int i = idx - h * NTOK;
        Qs[i][h] = g_q[qb + idx];
        Ks[i][h] = g_k[qb + idx];
        Vs[i][h] = g_v[qb + idx];
    }
    __syncthreads();

    int wid = tid >> 5, lane = tid & 31;
    const float scale = 0.05103103630798288f;   // 1/sqrt(384)

    for (int i = wid; i < NTOK; i += 8) {
        // q pairs: 16 floats = 8 packed operands, loaded directly as 64-bit pairs
        ulonglong2 qq0 = *reinterpret_cast<const ulonglong2*>(&Qs[i][0]);
        ulonglong2 qq1 = *reinterpret_cast<const ulonglong2*>(&Qs[i][4]);
        ulonglong2 qq2 = *reinterpret_cast<const ulonglong2*>(&Qs[i][8]);
        ulonglong2 qq3 = *reinterpret_cast<const ulonglong2*>(&Qs[i][12]);

        float sv[7];
        float m = -1e30f;
#pragma unroll
        for (int t = 0; t < 7; t++) {
            int j = lane + t * 32;
            float s = -1e30f;
            if (j < NTOK) {
                ulonglong2 k0 = *reinterpret_cast<const ulonglong2*>(&Ks[j][0]);
                ulonglong2 k1 = *reinterpret_cast<const ulonglong2*>(&Ks[j][4]);
                ulonglong2 k2 = *reinterpret_cast<const ulonglong2*>(&Ks[j][8]);
                ulonglong2 k3 = *reinterpret_cast<const ulonglong2*>(&Ks[j][12]);
                unsigned long long d2 = 0ull;
                fma2(d2, qq0.x, k0.x); fma2(d2, qq0.y, k0.y);
                fma2(d2, qq1.x, k1.x); fma2(d2, qq1.y, k1.y);
                fma2(d2, qq2.x, k2.x); fma2(d2, qq2.y, k2.y);
                fma2(d2, qq3.x, k3.x); fma2(d2, qq3.y, k3.y);
                float lo, hi;
                unpack2(d2, lo, hi);
                s = (lo + hi) * scale;
            }
            sv[t] = s;
            m = fmaxf(m, s);
        }
#pragma unroll
        for (int off = 16; off; off >>= 1)
            m = fmaxf(m, __shfl_xor_sync(0xffffffffu, m, off));

        float sum = 0.f;
#pragma unroll
        for (int t = 0; t < 7; t++) {
            float e = __expf(sv[t] - m);   // lanes with j>=196 underflow to 0
            sv[t] = e;
            sum += e;
        }
#pragma unroll
        for (int off = 16; off; off >>= 1)
            sum += __shfl_xor_sync(0xffffffffu, sum, off);
        float inv = 1.0f / sum;

        unsigned long long o2[8] = {};          // 16 head accumulators, packed
        size_t prow = ((size_t)bc * NTOK + i) * NTOK;
#pragma unroll
        for (int t = 0; t < 7; t++) {
            int j = lane + t * 32;
            if (j < NTOK) {
                float p = sv[t] * inv;
                if (probs) __stcs(&probs[prow + j], p);   // streaming: never re-read, keep out of L2
                unsigned long long pp = pack2(p, p);
                ulonglong2 v0 = *reinterpret_cast<const ulonglong2*>(&Vs[j][0]);
                ulonglong2 v1 = *reinterpret_cast<const ulonglong2*>(&Vs[j][4]);
                ulonglong2 v2 = *reinterpret_cast<const ulonglong2*>(&Vs[j][8]);
                ulonglong2 v3 = *reinterpret_cast<const ulonglong2*>(&Vs[j][12]);
                fma2(o2[0], pp, v0.x); fma2(o2[1], pp, v0.y);
                fma2(o2[2], pp, v1.x); fma2(o2[3], pp, v1.y);
                fma2(o2[4], pp, v2.x); fma2(o2[5], pp, v2.y);
                fma2(o2[6], pp, v3.x); fma2(o2[7], pp, v3.y);
            }
        }
#pragma unroll
        for (int off = 16; off; off >>= 1)
#pragma unroll
            for (int h = 0; h < 8; h++)
                o2[h] = add2(o2[h], __shfl_xor_sync(0xffffffffu, o2[h], off));

        if (lane < 16) {
            float lo, hi;
            unpack2(o2[lane >> 1], lo, hi);
            float val = (lane & 1) ? hi : lo;
            int bb = bc / DMODEL;
            int c  = bc - bb * DMODEL;
            // K-permuted layout: k' = c*16 + h  -> 16 lanes write 64B contiguous
            g_attn[(size_t)(bb * NTOK + i) * HDIM + c * NHEADS + lane] = val;
        }
    }
}

// ---------------- Wout GEMM (split-K, double-buffered, packed f32x2) over permuted K ----
// A = g_attn [row][k'], k' = c*16+h. B rows permuted: orig Wout row = (k'&15)*384 + (k'>>4).
__global__ __launch_bounds__(256) void wout_gemm(const float* __restrict__ Wout) {
    __shared__ float As[2][8][128];
    __shared__ float Bs[2][8][128];

    int n0 = blockIdx.x * 128;            // 0..2
    int m0 = blockIdx.y * 128;            // 0..6
    int z  = blockIdx.z;                  // 0..SPLITK-1
    int kbase = z * (HDIM / SPLITK);      // 768 per chunk

    int tid = threadIdx.x;
    int tx = tid & 15, ty = tid >> 4;
    int ar   = tid >> 1;
    int ak   = (tid & 1) * 4;
    int arow = m0 + ar;
    int br   = tid >> 5;
    int bc4  = (tid & 31) * 4;

    unsigned long long acc2[8][4] = {};

    {
        float4 av = (arow < NROWS)
            ? *reinterpret_cast<const float4*>(&g_attn[(size_t)arow * HDIM + kbase + ak])
            : make_float4(0.f, 0.f, 0.f, 0.f);
        int kp = kbase + br;
        int r  = (kp & 15) * DMODEL + (kp >> 4);
        float4 bv = *reinterpret_cast<const float4*>(&Wout[(size_t)r * DMODEL + n0 + bc4]);
        As[0][ak + 0][ar] = av.x;
        As[0][ak + 1][ar] = av.y;
        As[0][ak + 2][ar] = av.z;
        As[0][ak + 3][ar] = av.w;
        *reinterpret_cast<float4*>(&Bs[0][br][bc4]) = bv;
    }
    __syncthreads();

    int buf = 0;
    for (int kt = 8; kt <= HDIM / SPLITK; kt += 8) {
        float4 av, bv;
        bool more = (kt < HDIM / SPLITK);
        if (more) {
            av = (arow < NROWS)
                ? *reinterpret_cast<const float4*>(&g_attn[(size_t)arow * HDIM + kbase + kt + ak])
                : make_float4(0.f, 0.f, 0.f, 0.f);
            int kp = kbase + kt + br;
            int r  = (kp & 15) * DMODEL + (kp >> 4);
            bv = *reinterpret_cast<const float4*>(&Wout[(size_t)r * DMODEL + n0 + bc4]);
        }
#pragma unroll
        for (int k = 0; k < 8; k++) {
            float4 a0 = *reinterpret_cast<const float4*>(&As[buf][k][tx * 8]);
            float4 a1 = *reinterpret_cast<const float4*>(&As[buf][k][tx * 8 + 4]);
            ulonglong2 bq0 = *reinterpret_cast<const ulonglong2*>(&Bs[buf][k][ty * 8]);
            ulonglong2 bq1 = *reinterpret_cast<const ulonglong2*>(&Bs[buf][k][ty * 8 + 4]);
            float a[8] = {a0.x, a0.y, a0.z, a0.w, a1.x, a1.y, a1.z, a1.w};
#pragma unroll
            for (int i = 0; i < 8; i++) {
                unsigned long long ap = pack2(a[i], a[i]);
                fma2(acc2[i][0], ap, bq0.x);
                fma2(acc2[i][1], ap, bq0.y);
                fma2(acc2[i][2], ap, bq1.x);
                fma2(acc2[i][3], ap, bq1.y);
            }
        }
        if (more) {
            int nb = buf ^ 1;
            As[nb][ak + 0][ar] = av.x;
            As[nb][ak + 1][ar] = av.y;
            As[nb][ak + 2][ar] = av.z;
            As[nb][ak + 3][ar] = av.w;
            *reinterpret_cast<float4*>(&Bs[nb][br][bc4]) = bv;
            __syncthreads();
            buf = nb;
        }
    }

    float acc[8][8];
#pragma unroll
    for (int i = 0; i < 8; i++)
#pragma unroll
        for (int jj = 0; jj < 4; jj++)
            unpack2(acc2[i][jj], acc[i][2 * jj], acc[i][2 * jj + 1]);

#pragma unroll
    for (int i = 0; i < 8; i++) {
        int row = m0 + tx * 8 + i;
        if (row < NROWS) {
            float* dst = &g_part[z][(size_t)row * DMODEL + n0 + ty * 8];
#pragma unroll
            for (int j = 0; j < 8; j++) dst[j] = acc[i][j];
        }
    }
}

// ---------------- final reduce: out = xn + sum_z partial[z], float4 vectorized ----------------
__global__ void reduce_kernel(float* __restrict__ out) {
    int idx = (blockIdx.x * 256 + threadIdx.x) * 4;   // grid covers exactly 301056 floats
    float4 s = *reinterpret_cast<const float4*>(&g_xn[idx]);
#pragma unroll
    for (int z = 0; z < SPLITK; z++) {
        float4 p = *reinterpret_cast<const float4*>(&g_part[z][idx]);
        s.x += p.x; s.y += p.y; s.z += p.z; s.w += p.w;
    }
    *reinterpret_cast<float4*>(&out[idx]) = s;
}

// ---------------- launch ----------------
extern "C" void kernel_launch(void* const* d_in, const int* in_sizes, int n_in,
                              void* d_out, int out_size) {
    const float* x     = (const float*)d_in[0];
    const float* Wq    = (const float*)d_in[1];
    const float* Wk    = (const float*)d_in[2];
    const float* Wv    = (const float*)d_in[3];
    const float* Wout  = (const float*)d_in[4];
    const float* gamma = (const float*)d_in[5];
    const float* beta  = (const float*)d_in[6];

    float* out   = (float*)d_out;
    // output tuple = (out, probs) flattened: out first (301056), probs after (58982400)
    float* probs = (out_size >= NROWS * DMODEL + NBC * NTOK * NTOK)
                 ? out + NROWS * DMODEL : nullptr;

    ln_kernel<<<NROWS, 128>>>(x, gamma, beta);

    dim3 pgrid(HDIM / 128, (NROWS + 127) / 128, 3);     // 48 x 7 x 3
    proj_gemm<<<pgrid, 256>>>(Wq, Wk, Wv);

    attn_kernel<<<NBC, 256>>>(probs);

    dim3 wgrid(DMODEL / 128, (NROWS + 127) / 128, SPLITK);   // 3 x 7 x 8
    wout_gemm<<<wgrid, 256>>>(Wout);

    reduce_kernel<<<(NROWS * DMODEL) / 1024, 256>>>(out);
}

// round 10
// speedup vs baseline: 1.0221x; 1.0221x over previous
#include <cuda_runtime.h>
#include <cstddef>

#define NTOK   196
#define DMODEL 384
#define NHEADS 16
#define HDIM   6144
#define NBATCH 4
#define NROWS  784          // NBATCH * NTOK
#define NBC    1536         // NBATCH * DMODEL
#define SPLITK 16

// ---------------- scratch (static __device__, no allocation) ----------------
__device__ float g_xn[NROWS * DMODEL];                         // 1.2 MB
// qkv layout: [b][c][h][i]  (per (b,c): 16*196 contiguous floats)
__device__ float g_q[(size_t)NBC * NHEADS * NTOK];             // 19.3 MB
__device__ float g_k[(size_t)NBC * NHEADS * NTOK];
__device__ float g_v[(size_t)NBC * NHEADS * NTOK];
// attn out layout: [row][ c*16 + h ]  (K-permuted for dense 64B writes)
__device__ float g_attn[(size_t)NROWS * HDIM];                 // 19.3 MB
__device__ float g_part[SPLITK][NROWS * DMODEL];               // 19.3 MB

// ---------------- packed f32x2 helpers (sm_100+; ptxas never emits FFMA2 from C++) ----
__device__ __forceinline__ unsigned long long pack2(float lo, float hi) {
    unsigned long long r;
    asm("mov.b64 %0, {%1, %2};" : "=l"(r) : "f"(lo), "f"(hi));
    return r;
}
__device__ __forceinline__ void fma2(unsigned long long& d,
                                     unsigned long long a, unsigned long long b) {
    asm("fma.rn.f32x2 %0, %1, %2, %0;" : "+l"(d) : "l"(a), "l"(b));
}
__device__ __forceinline__ unsigned long long add2(unsigned long long a,
                                                   unsigned long long b) {
    unsigned long long r;
    asm("add.rn.f32x2 %0, %1, %2;" : "=l"(r) : "l"(a), "l"(b));
    return r;
}
__device__ __forceinline__ void unpack2(unsigned long long v, float& lo, float& hi) {
    asm("mov.b64 {%0, %1}, %2;" : "=f"(lo), "=f"(hi) : "l"(v));
}

// ---------------- LayerNorm ----------------
__global__ void ln_kernel(const float* __restrict__ x,
                          const float* __restrict__ gamma,
                          const float* __restrict__ beta) {
    int row = blockIdx.x;
    int tid = threadIdx.x;                 // 128 threads
    const float* xr = x + (size_t)row * DMODEL;

    float v[3];
    float s = 0.f, s2 = 0.f;
#pragma unroll
    for (int t = 0; t < 3; t++) {
        float val = xr[tid + t * 128];
        v[t] = val;
        s  += val;
        s2 += val * val;
    }
#pragma unroll
    for (int off = 16; off; off >>= 1) {
        s  += __shfl_xor_sync(0xffffffffu, s,  off);
        s2 += __shfl_xor_sync(0xffffffffu, s2, off);
    }
    __shared__ float red[2][4];
    int wid = tid >> 5, lane = tid & 31;
    if (lane == 0) { red[0][wid] = s; red[1][wid] = s2; }
    __syncthreads();
    s  = red[0][0] + red[0][1] + red[0][2] + red[0][3];
    s2 = red[1][0] + red[1][1] + red[1][2] + red[1][3];

    float mu  = s * (1.f / DMODEL);
    float var = s2 * (1.f / DMODEL) - mu * mu;
    float inv = rsqrtf(var + 1e-5f);
#pragma unroll
    for (int t = 0; t < 3; t++) {
        int c = tid + t * 128;
        g_xn[(size_t)row * DMODEL + c] = (v[t] - mu) * inv * gamma[c] + beta[c];
    }
}

// ---------------- Fused projection GEMM: xn(784x384) @ W(384x6144), z selects Wq/Wk/Wv ----
// BM=BN=128, BK=16, 256 threads, 8x8 microtile (packed f32x2), double-buffered smem.
// Output: [b][c][h][i] — dense float4 stores per output column.
__global__ __launch_bounds__(256, 2) void proj_gemm(const float* __restrict__ Wq,
                                                    const float* __restrict__ Wk,
                                                    const float* __restrict__ Wv) {
    int which = blockIdx.z;
    const float* W = (which == 0) ? Wq : (which == 1) ? Wk : Wv;
    float* outp    = (which == 0) ? g_q : (which == 1) ? g_k : g_v;

    __shared__ float As[2][16][128];
    __shared__ float Bs[2][16][128];

    int n0 = blockIdx.x * 128;
    int m0 = blockIdx.y * 128;
    int tid = threadIdx.x;
    int tx = tid & 15;        // row group
    int ty = tid >> 4;        // col group

    int ar   = tid >> 1;            // 0..127
    int ak   = (tid & 1) * 4;       // 0 or 4 (plus +8 for second half)
    int arow = m0 + ar;
    int br   = tid >> 5;            // 0..7 (plus +8 for second half)
    int bc4  = (tid & 31) * 4;      // 0..124

    unsigned long long acc2[8][4] = {};   // (0.f,0.f) == 0ull

    {   // prologue: tile 0 (k = 0..15)
        float4 a0v, a1v;
        if (arow < NROWS) {
            a0v = *reinterpret_cast<const float4*>(&g_xn[(size_t)arow * DMODEL + ak]);
            a1v = *reinterpret_cast<const float4*>(&g_xn[(size_t)arow * DMODEL + ak + 8]);
        } else { a0v = a1v = make_float4(0.f, 0.f, 0.f, 0.f); }
        float4 b0v = *reinterpret_cast<const float4*>(&W[(size_t)br * HDIM + n0 + bc4]);
        float4 b1v = *reinterpret_cast<const float4*>(&W[(size_t)(br + 8) * HDIM + n0 + bc4]);
        As[0][ak + 0][ar] = a0v.x; As[0][ak + 1][ar] = a0v.y;
        As[0][ak + 2][ar] = a0v.z; As[0][ak + 3][ar] = a0v.w;
        As[0][ak + 8][ar] = a1v.x; As[0][ak + 9][ar] = a1v.y;
        As[0][ak + 10][ar] = a1v.z; As[0][ak + 11][ar] = a1v.w;
        *reinterpret_cast<float4*>(&Bs[0][br][bc4])     = b0v;
        *reinterpret_cast<float4*>(&Bs[0][br + 8][bc4]) = b1v;
    }
    __syncthreads();

    int buf = 0;
    for (int kt = 16; kt <= DMODEL; kt += 16) {
        float4 a0v, a1v, b0v, b1v;
        bool more = (kt < DMODEL);
        if (more) {
            if (arow < NROWS) {
                a0v = *reinterpret_cast<const float4*>(&g_xn[(size_t)arow * DMODEL + kt + ak]);
                a1v = *reinterpret_cast<const float4*>(&g_xn[(size_t)arow * DMODEL + kt + ak + 8]);
            } else { a0v = a1v = make_float4(0.f, 0.f, 0.f, 0.f); }
            b0v = *reinterpret_cast<const float4*>(&W[(size_t)(kt + br) * HDIM + n0 + bc4]);
            b1v = *reinterpret_cast<const float4*>(&W[(size_t)(kt + br + 8) * HDIM + n0 + bc4]);
        }
#pragma unroll
        for (int k = 0; k < 16; k++) {
            float4 a0 = *reinterpret_cast<const float4*>(&As[buf][k][tx * 8]);
            float4 a1 = *reinterpret_cast<const float4*>(&As[buf][k][tx * 8 + 4]);
            ulonglong2 bq0 = *reinterpret_cast<const ulonglong2*>(&Bs[buf][k][ty * 8]);
            ulonglong2 bq1 = *reinterpret_cast<const ulonglong2*>(&Bs[buf][k][ty * 8 + 4]);
            float a[8] = {a0.x, a0.y, a0.z, a0.w, a1.x, a1.y, a1.z, a1.w};
#pragma unroll
            for (int i = 0; i < 8; i++) {
                unsigned long long ap = pack2(a[i], a[i]);
                fma2(acc2[i][0], ap, bq0.x);
                fma2(acc2[i][1], ap, bq0.y);
                fma2(acc2[i][2], ap, bq1.x);
                fma2(acc2[i][3], ap, bq1.y);
            }
        }
        if (more) {
            int nb = buf ^ 1;
            As[nb][ak + 0][ar] = a0v.x; As[nb][ak + 1][ar] = a0v.y;
            As[nb][ak + 2][ar] = a0v.z; As[nb][ak + 3][ar] = a0v.w;
            As[nb][ak + 8][ar] = a1v.x; As[nb][ak + 9][ar] = a1v.y;
            As[nb][ak + 10][ar] = a1v.z; As[nb][ak + 11][ar] = a1v.w;
            *reinterpret_cast<float4*>(&Bs[nb][br][bc4])     = b0v;
            *reinterpret_cast<float4*>(&Bs[nb][br + 8][bc4]) = b1v;
            __syncthreads();
            buf = nb;
        }
    }

    // unpack accumulators
    float acc[8][8];
#pragma unroll
    for (int i = 0; i < 8; i++)
#pragma unroll
        for (int jj = 0; jj < 4; jj++)
            unpack2(acc2[i][jj], acc[i][2 * jj], acc[i][2 * jj + 1]);

    // epilogue: col j_glob = n0 + ty*8 + j lies in one h (384 = 3*128 tiles).
    // address = ((b*DMODEL + c)*NHEADS + h)*NTOK + i
    int h  = n0 / DMODEL;
    int cb = n0 - h * DMODEL + ty * 8;
    int rbase = m0 + tx * 8;
    int bfirst = rbase / NTOK;
    int blast  = (rbase + 7) / NTOK;
    if (rbase + 7 < NROWS && bfirst == blast) {
        int ii0 = rbase - bfirst * NTOK;           // multiple of 4 -> float4 aligned
#pragma unroll
        for (int j = 0; j < 8; j++) {
            int c = cb + j;
            float* dst = &outp[((size_t)(bfirst * DMODEL + c) * NHEADS + h) * NTOK + ii0];
            *reinterpret_cast<float4*>(dst)     = make_float4(acc[0][j], acc[1][j], acc[2][j], acc[3][j]);
            *reinterpret_cast<float4*>(dst + 4) = make_float4(acc[4][j], acc[5][j], acc[6][j], acc[7][j]);
        }
    } else {
#pragma unroll
        for (int i = 0; i < 8; i++) {
            int row = rbase + i;
            if (row < NROWS) {
                int b  = row / NTOK;
                int ii = row - b * NTOK;
#pragma unroll
                for (int j = 0; j < 8; j++) {
                    int c = cb + j;
                    outp[((size_t)(b * DMODEL + c) * NHEADS + h) * NTOK + ii] = acc[i][j];
                }
            }
        }
    }
}

// ---------------- Channel attention: one block per (b,c), packed f32x2 math ----------------
__global__ __launch_bounds__(256) void attn_kernel(float* __restrict__ probs) {
    int bc = blockIdx.x;                   // b*384 + c
    __shared__ float Qs[NTOK][16];
    __shared__ float Ks[NTOK][20];         // 80B row stride: 16B-aligned, LDS.128 conflict-free
    __shared__ float Vs[NTOK][20];

    int tid = threadIdx.x;
    size_t qb = (size_t)bc * (NTOK * NHEADS);
    // memory layout [h][i]; smem layout [i][h]. Global reads stay contiguous.
    for (int idx = tid; idx < NTOK * NHEADS; idx += 256) {
        int h = idx / NTOK;
        int i = idx - h * NTOK;
        Qs[i][h] = g_q[qb + idx];
        Ks[i][h] = g_k[qb + idx];
        Vs[i][h] = g_v[qb + idx];
    }
    __syncthreads();

    int wid = tid >> 5, lane = tid & 31;
    const float scale = 0.05103103630798288f;   // 1/sqrt(384)

    for (int i = wid; i < NTOK; i += 8) {
        // q pairs: 16 floats = 8 packed operands, loaded directly as 64-bit pairs
        ulonglong2 qq0 = *reinterpret_cast<const ulonglong2*>(&Qs[i][0]);
        ulonglong2 qq1 = *reinterpret_cast<const ulonglong2*>(&Qs[i][4]);
        ulonglong2 qq2 = *reinterpret_cast<const ulonglong2*>(&Qs[i][8]);
        ulonglong2 qq3 = *reinterpret_cast<const ulonglong2*>(&Qs[i][12]);

        float sv[7];
        float m = -1e30f;
#pragma unroll
        for (int t = 0; t < 7; t++) {
            int j = lane + t * 32;
            float s = -1e30f;
            if (j < NTOK) {
                ulonglong2 k0 = *reinterpret_cast<const ulonglong2*>(&Ks[j][0]);
                ulonglong2 k1 = *reinterpret_cast<const ulonglong2*>(&Ks[j][4]);
                ulonglong2 k2 = *reinterpret_cast<const ulonglong2*>(&Ks[j][8]);
                ulonglong2 k3 = *reinterpret_cast<const ulonglong2*>(&Ks[j][12]);
                unsigned long long d2 = 0ull;
                fma2(d2, qq0.x, k0.x); fma2(d2, qq0.y, k0.y);
                fma2(d2, qq1.x, k1.x); fma2(d2, qq1.y, k1.y);
                fma2(d2, qq2.x, k2.x); fma2(d2, qq2.y, k2.y);
                fma2(d2, qq3.x, k3.x); fma2(d2, qq3.y, k3.y);
                float lo, hi;
                unpack2(d2, lo, hi);
                s = (lo + hi) * scale;
            }
            sv[t] = s;
            m = fmaxf(m, s);
        }
#pragma unroll
        for (int off = 16; off; off >>= 1)
            m = fmaxf(m, __shfl_xor_sync(0xffffffffu, m, off));

        float sum = 0.f;
#pragma unroll
        for (int t = 0; t < 7; t++) {
            float e = __expf(sv[t] - m);   // lanes with j>=196 underflow to 0
            sv[t] = e;
            sum += e;
        }
#pragma unroll
        for (int off = 16; off; off >>= 1)
            sum += __shfl_xor_sync(0xffffffffu, sum, off);
        float inv = 1.0f / sum;

        unsigned long long o2[8] = {};          // 16 head accumulators, packed
        size_t prow = ((size_t)bc * NTOK + i) * NTOK;
#pragma unroll
        for (int t = 0; t < 7; t++) {
            int j = lane + t * 32;
            if (j < NTOK) {
                float p = sv[t] * inv;
                if (probs) __stcs(&probs[prow + j], p);   // streaming: never re-read
                unsigned long long pp = pack2(p, p);
                ulonglong2 v0 = *reinterpret_cast<const ulonglong2*>(&Vs[j][0]);
                ulonglong2 v1 = *reinterpret_cast<const ulonglong2*>(&Vs[j][4]);
                ulonglong2 v2 = *reinterpret_cast<const ulonglong2*>(&Vs[j][8]);
                ulonglong2 v3 = *reinterpret_cast<const ulonglong2*>(&Vs[j][12]);
                fma2(o2[0], pp, v0.x); fma2(o2[1], pp, v0.y);
                fma2(o2[2], pp, v1.x); fma2(o2[3], pp, v1.y);
                fma2(o2[4], pp, v2.x); fma2(o2[5], pp, v2.y);
                fma2(o2[6], pp, v3.x); fma2(o2[7], pp, v3.y);
            }
        }
#pragma unroll
        for (int off = 16; off; off >>= 1)
#pragma unroll
            for (int h = 0; h < 8; h++)
                o2[h] = add2(o2[h], __shfl_xor_sync(0xffffffffu, o2[h], off));

        if (lane < 16) {
            float lo, hi;
            unpack2(o2[lane >> 1], lo, hi);
            float val = (lane & 1) ? hi : lo;
            int bb = bc / DMODEL;
            int c  = bc - bb * DMODEL;
            // K-permuted layout: k' = c*16 + h  -> 16 lanes write 64B contiguous
            g_attn[(size_t)(bb * NTOK + i) * HDIM + c * NHEADS + lane] = val;
        }
    }
}

// ---------------- Wout GEMM (split-K=16, BK=16, double-buffered, packed f32x2) ----------
// A = g_attn [row][k'], k' = c*16+h. B rows permuted: orig Wout row = (k'&15)*384 + (k'>>4).
__global__ __launch_bounds__(256, 2) void wout_gemm(const float* __restrict__ Wout) {
    __shared__ float As[2][16][128];
    __shared__ float Bs[2][16][128];

    int n0 = blockIdx.x * 128;            // 0..2
    int m0 = blockIdx.y * 128;            // 0..6
    int z  = blockIdx.z;                  // 0..SPLITK-1
    int kbase = z * (HDIM / SPLITK);      // 384 per chunk

    int tid = threadIdx.x;
    int tx = tid & 15, ty = tid >> 4;
    int ar   = tid >> 1;
    int ak   = (tid & 1) * 4;
    int arow = m0 + ar;
    int br   = tid >> 5;
    int bc4  = (tid & 31) * 4;

    unsigned long long acc2[8][4] = {};

    {
        float4 a0v, a1v;
        if (arow < NROWS) {
            a0v = *reinterpret_cast<const float4*>(&g_attn[(size_t)arow * HDIM + kbase + ak]);
            a1v = *reinterpret_cast<const float4*>(&g_attn[(size_t)arow * HDIM + kbase + ak + 8]);
        } else { a0v = a1v = make_float4(0.f, 0.f, 0.f, 0.f); }
        int kp0 = kbase + br;
        int kp1 = kbase + br + 8;
        int r0  = (kp0 & 15) * DMODEL + (kp0 >> 4);
        int r1  = (kp1 & 15) * DMODEL + (kp1 >> 4);
        float4 b0v = *reinterpret_cast<const float4*>(&Wout[(size_t)r0 * DMODEL + n0 + bc4]);
        float4 b1v = *reinterpret_cast<const float4*>(&Wout[(size_t)r1 * DMODEL + n0 + bc4]);
        As[0][ak + 0][ar] = a0v.x; As[0][ak + 1][ar] = a0v.y;
        As[0][ak + 2][ar] = a0v.z; As[0][ak + 3][ar] = a0v.w;
        As[0][ak + 8][ar] = a1v.x; As[0][ak + 9][ar] = a1v.y;
        As[0][ak + 10][ar] = a1v.z; As[0][ak + 11][ar] = a1v.w;
        *reinterpret_cast<float4*>(&Bs[0][br][bc4])     = b0v;
        *reinterpret_cast<float4*>(&Bs[0][br + 8][bc4]) = b1v;
    }
    __syncthreads();

    int buf = 0;
    for (int kt = 16; kt <= HDIM / SPLITK; kt += 16) {
        float4 a0v, a1v, b0v, b1v;
        bool more = (kt < HDIM / SPLITK);
        if (more) {
            if (arow < NROWS) {
                a0v = *reinterpret_cast<const float4*>(&g_attn[(size_t)arow * HDIM + kbase + kt + ak]);
                a1v = *reinterpret_cast<const float4*>(&g_attn[(size_t)arow * HDIM + kbase + kt + ak + 8]);
            } else { a0v = a1v = make_float4(0.f, 0.f, 0.f, 0.f); }
            int kp0 = kbase + kt + br;
            int kp1 = kbase + kt + br + 8;
            int r0  = (kp0 & 15) * DMODEL + (kp0 >> 4);
            int r1  = (kp1 & 15) * DMODEL + (kp1 >> 4);
            b0v = *reinterpret_cast<const float4*>(&Wout[(size_t)r0 * DMODEL + n0 + bc4]);
            b1v = *reinterpret_cast<const float4*>(&Wout[(size_t)r1 * DMODEL + n0 + bc4]);
        }
#pragma unroll
        for (int k = 0; k < 16; k++) {
            float4 a0 = *reinterpret_cast<const float4*>(&As[buf][k][tx * 8]);
            float4 a1 = *reinterpret_cast<const float4*>(&As[buf][k][tx * 8 + 4]);
            ulonglong2 bq0 = *reinterpret_cast<const ulonglong2*>(&Bs[buf][k][ty * 8]);
            ulonglong2 bq1 = *reinterpret_cast<const ulonglong2*>(&Bs[buf][k][ty * 8 + 4]);
            float a[8] = {a0.x, a0.y, a0.z, a0.w, a1.x, a1.y, a1.z, a1.w};
#pragma unroll
            for (int i = 0; i < 8; i++) {
                unsigned long long ap = pack2(a[i], a[i]);
                fma2(acc2[i][0], ap, bq0.x);
                fma2(acc2[i][1], ap, bq0.y);
                fma2(acc2[i][2], ap, bq1.x);
                fma2(acc2[i][3], ap, bq1.y);
            }
        }
        if (more) {
            int nb = buf ^ 1;
            As[nb][ak + 0][ar] = a0v.x; As[nb][ak + 1][ar] = a0v.y;
            As[nb][ak + 2][ar] = a0v.z; As[nb][ak + 3][ar] = a0v.w;
            As[nb][ak + 8][ar] = a1v.x; As[nb][ak + 9][ar] = a1v.y;
            As[nb][ak + 10][ar] = a1v.z; As[nb][ak + 11][ar] = a1v.w;
            *reinterpret_cast<float4*>(&Bs[nb][br][bc4])     = b0v;
            *reinterpret_cast<float4*>(&Bs[nb][br + 8][bc4]) = b1v;
            __syncthreads();
            buf = nb;
        }
    }

    float acc[8][8];
#pragma unroll
    for (int i = 0; i < 8; i++)
#pragma unroll
        for (int jj = 0; jj < 4; jj++)
            unpack2(acc2[i][jj], acc[i][2 * jj], acc[i][2 * jj + 1]);

#pragma unroll
    for (int i = 0; i < 8; i++) {
        int row = m0 + tx * 8 + i;
        if (row < NROWS) {
            float* dst = &g_part[z][(size_t)row * DMODEL + n0 + ty * 8];
#pragma unroll
            for (int j = 0; j < 8; j++) dst[j] = acc[i][j];
        }
    }
}

// ---------------- final reduce: out = xn + sum_z partial[z], float4 vectorized ----------------
__global__ void reduce_kernel(float* __restrict__ out) {
    int idx = (blockIdx.x * 256 + threadIdx.x) * 4;   // grid covers exactly 301056 floats
    float4 s = *reinterpret_cast<const float4*>(&g_xn[idx]);
#pragma unroll
    for (int z = 0; z < SPLITK; z++) {
        float4 p = *reinterpret_cast<const float4*>(&g_part[z][idx]);
        s.x += p.x; s.y += p.y; s.z += p.z; s.w += p.w;
    }
    *reinterpret_cast<float4*>(&out[idx]) = s;
}

// ---------------- launch ----------------
extern "C" void kernel_launch(void* const* d_in, const int* in_sizes, int n_in,
                              void* d_out, int out_size) {
    const float* x     = (const float*)d_in[0];
    const float* Wq    = (const float*)d_in[1];
    const float* Wk    = (const float*)d_in[2];
    const float* Wv    = (const float*)d_in[3];
    const float* Wout  = (const float*)d_in[4];
    const float* gamma = (const float*)d_in[5];
    const float* beta  = (const float*)d_in[6];

    float* out   = (float*)d_out;
    // output tuple = (out, probs) flattened: out first (301056), probs after (58982400)
    float* probs = (out_size >= NROWS * DMODEL + NBC * NTOK * NTOK)
                 ? out + NROWS * DMODEL : nullptr;

    ln_kernel<<<NROWS, 128>>>(x, gamma, beta);

    dim3 pgrid(HDIM / 128, (NROWS + 127) / 128, 3);     // 48 x 7 x 3
    proj_gemm<<<pgrid, 256>>>(Wq, Wk, Wv);

    attn_kernel<<<NBC, 256>>>(probs);

    dim3 wgrid(DMODEL / 128, (NROWS + 127) / 128, SPLITK);   // 3 x 7 x 16
    wout_gemm<<<wgrid, 256>>>(Wout);

    reduce_kernel<<<(NROWS * DMODEL) / 1024, 256>>>(out);
}

// round 13
// speedup vs baseline: 1.0942x; 1.0706x over previous
#include <cuda_runtime.h>
#include <cstddef>

#define NTOK   196
#define DMODEL 384
#define NHEADS 16
#define HDIM   6144
#define NBATCH 4
#define NROWS  784          // NBATCH * NTOK
#define NBC    1536         // NBATCH * DMODEL
#define SPLITK 16

// ---------------- scratch (static __device__, no allocation) ----------------
__device__ float g_xn[NROWS * DMODEL];                         // 1.2 MB
// qkv layout: [b][c][h][i]  (per (b,c): 16*196 contiguous floats)
__device__ float g_q[(size_t)NBC * NHEADS * NTOK];             // 19.3 MB
__device__ float g_k[(size_t)NBC * NHEADS * NTOK];
__device__ float g_v[(size_t)NBC * NHEADS * NTOK];
// attn out layout: [row][ c*16 + h ]  (K-permuted for dense 64B writes)
__device__ float g_attn[(size_t)NROWS * HDIM];                 // 19.3 MB
__device__ float g_part[SPLITK][NROWS * DMODEL];               // 19.3 MB

// ---------------- packed f32x2 helpers (sm_100+; ptxas never emits FFMA2 from C++) ----
__device__ __forceinline__ unsigned long long pack2(float lo, float hi) {
    unsigned long long r;
    asm("mov.b64 %0, {%1, %2};" : "=l"(r) : "f"(lo), "f"(hi));
    return r;
}
__device__ __forceinline__ void fma2(unsigned long long& d,
                                     unsigned long long a, unsigned long long b) {
    asm("fma.rn.f32x2 %0, %1, %2, %0;" : "+l"(d) : "l"(a), "l"(b));
}
__device__ __forceinline__ unsigned long long add2(unsigned long long a,
                                                   unsigned long long b) {
    unsigned long long r;
    asm("add.rn.f32x2 %0, %1, %2;" : "=l"(r) : "l"(a), "l"(b));
    return r;
}
__device__ __forceinline__ void unpack2(unsigned long long v, float& lo, float& hi) {
    asm("mov.b64 {%0, %1}, %2;" : "=f"(lo), "=f"(hi) : "l"(v));
}

// ---------------- cp.async helpers ----------------
__device__ __forceinline__ unsigned int smem_u32(const void* p) {
    unsigned int r;
    asm("{ .reg .u64 t; cvta.to.shared.u64 t, %1; cvt.u32.u64 %0, t; }"
        : "=r"(r) : "l"(p));
    return r;
}
__device__ __forceinline__ void cp_async16(unsigned int dst, const void* src) {
    asm volatile("cp.async.cg.shared.global [%0], [%1], 16;\n"
                 :: "r"(dst), "l"(src) : "memory");
}
#define CP_COMMIT() asm volatile("cp.async.commit_group;\n" ::: "memory")
#define CP_WAIT1()  asm volatile("cp.async.wait_group 1;\n" ::: "memory")

// ---------------- LayerNorm ----------------
__global__ void ln_kernel(const float* __restrict__ x,
                          const float* __restrict__ gamma,
                          const float* __restrict__ beta) {
    int row = blockIdx.x;
    int tid = threadIdx.x;                 // 128 threads
    const float* xr = x + (size_t)row * DMODEL;

    float v[3];
    float s = 0.f, s2 = 0.f;
#pragma unroll
    for (int t = 0; t < 3; t++) {
        float val = xr[tid + t * 128];
        v[t] = val;
        s  += val;
        s2 += val * val;
    }
#pragma unroll
    for (int off = 16; off; off >>= 1) {
        s  += __shfl_xor_sync(0xffffffffu, s,  off);
        s2 += __shfl_xor_sync(0xffffffffu, s2, off);
    }
    __shared__ float red[2][4];
    int wid = tid >> 5, lane = tid & 31;
    if (lane == 0) { red[0][wid] = s; red[1][wid] = s2; }
    __syncthreads();
    s  = red[0][0] + red[0][1] + red[0][2] + red[0][3];
    s2 = red[1][0] + red[1][1] + red[1][2] + red[1][3];

    float mu  = s * (1.f / DMODEL);
    float var = s2 * (1.f / DMODEL) - mu * mu;
    float inv = rsqrtf(var + 1e-5f);
#pragma unroll
    for (int t = 0; t < 3; t++) {
        int c = tid + t * 128;
        g_xn[(size_t)row * DMODEL + c] = (v[t] - mu) * inv * gamma[c] + beta[c];
    }
}

// ---------------- Fused projection GEMM: xn(784x384) @ W(384x6144), z selects Wq/Wk/Wv ----
// BM=BN=128, BK=16, 256 threads, 8x8 microtile (packed f32x2).
// A: register double-buffer (L2-hot). B: cp.async 3-stage pipeline (DRAM stream).
__global__ __launch_bounds__(256, 2) void proj_gemm(const float* __restrict__ Wq,
                                                    const float* __restrict__ Wk,
                                                    const float* __restrict__ Wv) {
    int which = blockIdx.z;
    const float* W = (which == 0) ? Wq : (which == 1) ? Wk : Wv;
    float* outp    = (which == 0) ? g_q : (which == 1) ? g_k : g_v;

    __shared__ float As[2][16][128];
    __shared__ float Bs[3][16][128];

    int n0 = blockIdx.x * 128;
    int m0 = blockIdx.y * 128;
    int tid = threadIdx.x;
    int tx = tid & 15;        // row group
    int ty = tid >> 4;        // col group

    int ar   = tid >> 1;            // 0..127
    int ak   = (tid & 1) * 4;       // 0 or 4 (plus +8 for second half)
    int arow = m0 + ar;

    // B cp.async coords: 2 units of 16B per thread per stage
    int br0  = tid >> 5;            // rows 0..7
    int br1  = br0 + 8;             // rows 8..15
    int bcf  = (tid & 31) * 4;      // float offset 0..124

    unsigned long long acc2[8][4] = {};   // (0.f,0.f) == 0ull
    const int NK = DMODEL / 16;           // 24

    // --- prologue: B stages 0,1 via cp.async; A tile 0 via regs+STS ---
    cp_async16(smem_u32(&Bs[0][br0][bcf]), &W[(size_t)br0 * HDIM + n0 + bcf]);
    cp_async16(smem_u32(&Bs[0][br1][bcf]), &W[(size_t)br1 * HDIM + n0 + bcf]);
    CP_COMMIT();
    cp_async16(smem_u32(&Bs[1][br0][bcf]), &W[(size_t)(16 + br0) * HDIM + n0 + bcf]);
    cp_async16(smem_u32(&Bs[1][br1][bcf]), &W[(size_t)(16 + br1) * HDIM + n0 + bcf]);
    CP_COMMIT();
    {
        float4 a0v, a1v;
        if (arow < NROWS) {
            a0v = *reinterpret_cast<const float4*>(&g_xn[(size_t)arow * DMODEL + ak]);
            a1v = *reinterpret_cast<const float4*>(&g_xn[(size_t)arow * DMODEL + ak + 8]);
        } else { a0v = a1v = make_float4(0.f, 0.f, 0.f, 0.f); }
        As[0][ak + 0][ar] = a0v.x; As[0][ak + 1][ar] = a0v.y;
        As[0][ak + 2][ar] = a0v.z; As[0][ak + 3][ar] = a0v.w;
        As[0][ak + 8][ar] = a1v.x; As[0][ak + 9][ar] = a1v.y;
        As[0][ak + 10][ar] = a1v.z; As[0][ak + 11][ar] = a1v.w;
    }
    CP_WAIT1();            // stage 0 complete
    __syncthreads();

    int buf = 0;
    for (int it = 0; it < NK; ++it) {
        int kt = it * 16;
        float4 a0v, a1v;
        bool more = (it + 1 < NK);
        if (more) {
            if (arow < NROWS) {
                a0v = *reinterpret_cast<const float4*>(&g_xn[(size_t)arow * DMODEL + kt + 16 + ak]);
                a1v = *reinterpret_cast<const float4*>(&g_xn[(size_t)arow * DMODEL + kt + 16 + ak + 8]);
            } else { a0v = a1v = make_float4(0.f, 0.f, 0.f, 0.f); }
        }
        if (it + 2 < NK) {
            int s  = (it + 2) % 3;
            int kb = kt + 32;
            cp_async16(smem_u32(&Bs[s][br0][bcf]), &W[(size_t)(kb + br0) * HDIM + n0 + bcf]);
            cp_async16(smem_u32(&Bs[s][br1][bcf]), &W[(size_t)(kb + br1) * HDIM + n0 + bcf]);
        }
        CP_COMMIT();       // one group per iteration (possibly empty)

        int bs = it % 3;
#pragma unroll
        for (int k = 0; k < 16; k++) {
            float4 a0 = *reinterpret_cast<const float4*>(&As[buf][k][tx * 8]);
            float4 a1 = *reinterpret_cast<const float4*>(&As[buf][k][tx * 8 + 4]);
            ulonglong2 bq0 = *reinterpret_cast<const ulonglong2*>(&Bs[bs][k][ty * 8]);
            ulonglong2 bq1 = *reinterpret_cast<const ulonglong2*>(&Bs[bs][k][ty * 8 + 4]);
            float a[8] = {a0.x, a0.y, a0.z, a0.w, a1.x, a1.y, a1.z, a1.w};
#pragma unroll
            for (int i = 0; i < 8; i++) {
                unsigned long long ap = pack2(a[i], a[i]);
                fma2(acc2[i][0], ap, bq0.x);
                fma2(acc2[i][1], ap, bq0.y);
                fma2(acc2[i][2], ap, bq1.x);
                fma2(acc2[i][3], ap, bq1.y);
            }
        }
        if (more) {
            int nb = buf ^ 1;
            As[nb][ak + 0][ar] = a0v.x; As[nb][ak + 1][ar] = a0v.y;
            As[nb][ak + 2][ar] = a0v.z; As[nb][ak + 3][ar] = a0v.w;
            As[nb][ak + 8][ar] = a1v.x; As[nb][ak + 9][ar] = a1v.y;
            As[nb][ak + 10][ar] = a1v.z; As[nb][ak + 11][ar] = a1v.w;
            CP_WAIT1();    // next stage complete
            __syncthreads();
            buf = nb;
        }
    }

    // unpack accumulators
    float acc[8][8];
#pragma unroll
    for (int i = 0; i < 8; i++)
#pragma unroll
        for (int jj = 0; jj < 4; jj++)
            unpack2(acc2[i][jj], acc[i][2 * jj], acc[i][2 * jj + 1]);

    // epilogue: col j_glob = n0 + ty*8 + j lies in one h (384 = 3*128 tiles).
    // address = ((b*DMODEL + c)*NHEADS + h)*NTOK + i
    int h  = n0 / DMODEL;
    int cb = n0 - h * DMODEL + ty * 8;
    int rbase = m0 + tx * 8;
    int bfirst = rbase / NTOK;
    int blast  = (rbase + 7) / NTOK;
    if (rbase + 7 < NROWS && bfirst == blast) {
        int ii0 = rbase - bfirst * NTOK;           // multiple of 4 -> float4 aligned
#pragma unroll
        for (int j = 0; j < 8; j++) {
            int c = cb + j;
            float* dst = &outp[((size_t)(bfirst * DMODEL + c) * NHEADS + h) * NTOK + ii0];
            *reinterpret_cast<float4*>(dst)     = make_float4(acc[0][j], acc[1][j], acc[2][j], acc[3][j]);
            *reinterpret_cast<float4*>(dst + 4) = make_float4(acc[4][j], acc[5][j], acc[6][j], acc[7][j]);
        }
    } else {
#pragma unroll
        for (int i = 0; i < 8; i++) {
            int row = rbase + i;
            if (row < NROWS) {
                int b  = row / NTOK;
                int ii = row - b * NTOK;
#pragma unroll
                for (int j = 0; j < 8; j++) {
                    int c = cb + j;
                    outp[((size_t)(b * DMODEL + c) * NHEADS + h) * NTOK + ii] = acc[i][j];
                }
            }
        }
    }
}

// ---------------- Channel attention: one block per (b,c), packed f32x2 math ----------------
__global__ __launch_bounds__(256) void attn_kernel(float* __restrict__ probs) {
    int bc = blockIdx.x;                   // b*384 + c
    __shared__ float Qs[NTOK][16];
    __shared__ float Ks[NTOK][20];         // 80B row stride: 16B-aligned, LDS.128 conflict-free
    __shared__ float Vs[NTOK][20];

    int tid = threadIdx.x;
    size_t qb = (size_t)bc * (NTOK * NHEADS);
    // memory layout [h][i]; smem layout [i][h]. Global reads stay contiguous.
    for (int idx = tid; idx < NTOK * NHEADS; idx += 256) {
        int h = idx / NTOK;
        int i = idx - h * NTOK;
        Qs[i][h] = g_q[qb + idx];
        Ks[i][h] = g_k[qb + idx];
        Vs[i][h] = g_v[qb + idx];
    }
    __syncthreads();

    int wid = tid >> 5, lane = tid & 31;
    const float scale = 0.05103103630798288f;   // 1/sqrt(384)

    for (int i = wid; i < NTOK; i += 8) {
        // q pairs: 16 floats = 8 packed operands, loaded directly as 64-bit pairs
        ulonglong2 qq0 = *reinterpret_cast<const ulonglong2*>(&Qs[i][0]);
        ulonglong2 qq1 = *reinterpret_cast<const ulonglong2*>(&Qs[i][4]);
        ulonglong2 qq2 = *reinterpret_cast<const ulonglong2*>(&Qs[i][8]);
        ulonglong2 qq3 = *reinterpret_cast<const ulonglong2*>(&Qs[i][12]);

        float sv[7];
        float m = -1e30f;
#pragma unroll
        for (int t = 0; t < 7; t++) {
            int j = lane + t * 32;
            float s = -1e30f;
            if (j < NTOK) {
                ulonglong2 k0 = *reinterpret_cast<const ulonglong2*>(&Ks[j][0]);
                ulonglong2 k1 = *reinterpret_cast<const ulonglong2*>(&Ks[j][4]);
                ulonglong2 k2 = *reinterpret_cast<const ulonglong2*>(&Ks[j][8]);
                ulonglong2 k3 = *reinterpret_cast<const ulonglong2*>(&Ks[j][12]);
                unsigned long long d2 = 0ull;
                fma2(d2, qq0.x, k0.x); fma2(d2, qq0.y, k0.y);
                fma2(d2, qq1.x, k1.x); fma2(d2, qq1.y, k1.y);
                fma2(d2, qq2.x, k2.x); fma2(d2, qq2.y, k2.y);
                fma2(d2, qq3.x, k3.x); fma2(d2, qq3.y, k3.y);
                float lo, hi;
                unpack2(d2, lo, hi);
                s = (lo + hi) * scale;
            }
            sv[t] = s;
            m = fmaxf(m, s);
        }
#pragma unroll
        for (int off = 16; off; off >>= 1)
            m = fmaxf(m, __shfl_xor_sync(0xffffffffu, m, off));

        float sum = 0.f;
#pragma unroll
        for (int t = 0; t < 7; t++) {
            float e = __expf(sv[t] - m);   // lanes with j>=196 underflow to 0
            sv[t] = e;
            sum += e;
        }
#pragma unroll
        for (int off = 16; off; off >>= 1)
            sum += __shfl_xor_sync(0xffffffffu, sum, off);
        float inv = 1.0f / sum;

        unsigned long long o2[8] = {};          // 16 head accumulators, packed
        size_t prow = ((size_t)bc * NTOK + i) * NTOK;
#pragma unroll
        for (int t = 0; t < 7; t++) {
            int j = lane + t * 32;
            if (j < NTOK) {
                float p = sv[t] * inv;
                if (probs) __stcs(&probs[prow + j], p);   // streaming: never re-read
                unsigned long long pp = pack2(p, p);
                ulonglong2 v0 = *reinterpret_cast<const ulonglong2*>(&Vs[j][0]);
                ulonglong2 v1 = *reinterpret_cast<const ulonglong2*>(&Vs[j][4]);
                ulonglong2 v2 = *reinterpret_cast<const ulonglong2*>(&Vs[j][8]);
                ulonglong2 v3 = *reinterpret_cast<const ulonglong2*>(&Vs[j][12]);
                fma2(o2[0], pp, v0.x); fma2(o2[1], pp, v0.y);
                fma2(o2[2], pp, v1.x); fma2(o2[3], pp, v1.y);
                fma2(o2[4], pp, v2.x); fma2(o2[5], pp, v2.y);
                fma2(o2[6], pp, v3.x); fma2(o2[7], pp, v3.y);
            }
        }
#pragma unroll
        for (int off = 16; off; off >>= 1)
#pragma unroll
            for (int h = 0; h < 8; h++)
                o2[h] = add2(o2[h], __shfl_xor_sync(0xffffffffu, o2[h], off));

        if (lane < 16) {
            float lo, hi;
            unpack2(o2[lane >> 1], lo, hi);
            float val = (lane & 1) ? hi : lo;
            int bb = bc / DMODEL;
            int c  = bc - bb * DMODEL;
            // K-permuted layout: k' = c*16 + h  -> 16 lanes write 64B contiguous
            g_attn[(size_t)(bb * NTOK + i) * HDIM + c * NHEADS + lane] = val;
        }
    }
}

// ---------------- Wout GEMM (split-K=16, BK=16, cp.async B pipeline, packed f32x2) ------
// A = g_attn [row][k'], k' = c*16+h. B rows permuted: orig Wout row = (k'&15)*384 + (k'>>4).
__global__ __launch_bounds__(256, 2) void wout_gemm(const float* __restrict__ Wout) {
    __shared__ float As[2][16][128];
    __shared__ float Bs[3][16][128];

    int n0 = blockIdx.x * 128;            // 0..2
    int m0 = blockIdx.y * 128;            // 0..6
    int z  = blockIdx.z;                  // 0..SPLITK-1
    int kbase = z * (HDIM / SPLITK);      // 384 per chunk

    int tid = threadIdx.x;
    int tx = tid & 15, ty = tid >> 4;
    int ar   = tid >> 1;
    int ak   = (tid & 1) * 4;
    int arow = m0 + ar;

    int br0  = tid >> 5;
    int br1  = br0 + 8;
    int bcf  = (tid & 31) * 4;

    unsigned long long acc2[8][4] = {};
    const int NK = (HDIM / SPLITK) / 16;  // 24

    // --- prologue ---
    {
        int kp0 = kbase + br0, kp1 = kbase + br1;
        int r0 = (kp0 & 15) * DMODEL + (kp0 >> 4);
        int r1 = (kp1 & 15) * DMODEL + (kp1 >> 4);
        cp_async16(smem_u32(&Bs[0][br0][bcf]), &Wout[(size_t)r0 * DMODEL + n0 + bcf]);
        cp_async16(smem_u32(&Bs[0][br1][bcf]), &Wout[(size_t)r1 * DMODEL + n0 + bcf]);
        CP_COMMIT();
        kp0 += 16; kp1 += 16;
        r0 = (kp0 & 15) * DMODEL + (kp0 >> 4);
        r1 = (kp1 & 15) * DMODEL + (kp1 >> 4);
        cp_async16(smem_u32(&Bs[1][br0][bcf]), &Wout[(size_t)r0 * DMODEL + n0 + bcf]);
        cp_async16(smem_u32(&Bs[1][br1][bcf]), &Wout[(size_t)r1 * DMODEL + n0 + bcf]);
        CP_COMMIT();
    }
    {
        float4 a0v, a1v;
        if (arow < NROWS) {
            a0v = *reinterpret_cast<const float4*>(&g_attn[(size_t)arow * HDIM + kbase + ak]);
            a1v = *reinterpret_cast<const float4*>(&g_attn[(size_t)arow * HDIM + kbase + ak + 8]);
        } else { a0v = a1v = make_float4(0.f, 0.f, 0.f, 0.f); }
        As[0][ak + 0][ar] = a0v.x; As[0][ak + 1][ar] = a0v.y;
        As[0][ak + 2][ar] = a0v.z; As[0][ak + 3][ar] = a0v.w;
        As[0][ak + 8][ar] = a1v.x; As[0][ak + 9][ar] = a1v.y;
        As[0][ak + 10][ar] = a1v.z; As[0][ak + 11][ar] = a1v.w;
    }
    CP_WAIT1();
    __syncthreads();

    int buf = 0;
    for (int it = 0; it < NK; ++it) {
        int kt = it * 16;
        float4 a0v, a1v;
        bool more = (it + 1 < NK);
        if (more) {
            if (arow < NROWS) {
                a0v = *reinterpret_cast<const float4*>(&g_attn[(size_t)arow * HDIM + kbase + kt + 16 + ak]);
                a1v = *reinterpret_cast<const float4*>(&g_attn[(size_t)arow * HDIM + kbase + kt + 16 + ak + 8]);
            } else { a0v = a1v = make_float4(0.f, 0.f, 0.f, 0.f); }
        }
        if (it + 2 < NK) {
            int s  = (it + 2) % 3;
            int kp0 = kbase + kt + 32 + br0;
            int kp1 = kbase + kt + 32 + br1;
            int r0 = (kp0 & 15) * DMODEL + (kp0 >> 4);
            int r1 = (kp1 & 15) * DMODEL + (kp1 >> 4);
            cp_async16(smem_u32(&Bs[s][br0][bcf]), &Wout[(size_t)r0 * DMODEL + n0 + bcf]);
            cp_async16(smem_u32(&Bs[s][br1][bcf]), &Wout[(size_t)r1 * DMODEL + n0 + bcf]);
        }
        CP_COMMIT();

        int bs = it % 3;
#pragma unroll
        for (int k = 0; k < 16; k++) {
            float4 a0 = *reinterpret_cast<const float4*>(&As[buf][k][tx * 8]);
            float4 a1 = *reinterpret_cast<const float4*>(&As[buf][k][tx * 8 + 4]);
            ulonglong2 bq0 = *reinterpret_cast<const ulonglong2*>(&Bs[bs][k][ty * 8]);
            ulonglong2 bq1 = *reinterpret_cast<const ulonglong2*>(&Bs[bs][k][ty * 8 + 4]);
            float a[8] = {a0.x, a0.y, a0.z, a0.w, a1.x, a1.y, a1.z, a1.w};
#pragma unroll
            for (int i = 0; i < 8; i++) {
                unsigned long long ap = pack2(a[i], a[i]);
                fma2(acc2[i][0], ap, bq0.x);
                fma2(acc2[i][1], ap, bq0.y);
                fma2(acc2[i][2], ap, bq1.x);
                fma2(acc2[i][3], ap, bq1.y);
            }
        }
        if (more) {
            int nb = buf ^ 1;
            As[nb][ak + 0][ar] = a0v.x; As[nb][ak + 1][ar] = a0v.y;
            As[nb][ak + 2][ar] = a0v.z; As[nb][ak + 3][ar] = a0v.w;
            As[nb][ak + 8][ar] = a1v.x; As[nb][ak + 9][ar] = a1v.y;
            As[nb][ak + 10][ar] = a1v.z; As[nb][ak + 11][ar] = a1v.w;
            CP_WAIT1();
            __syncthreads();
            buf = nb;
        }
    }

    float acc[8][8];
#pragma unroll
    for (int i = 0; i < 8; i++)
#pragma unroll
        for (int jj = 0; jj < 4; jj++)
            unpack2(acc2[i][jj], acc[i][2 * jj], acc[i][2 * jj + 1]);

#pragma unroll
    for (int i = 0; i < 8; i++) {
        int row = m0 + tx * 8 + i;
        if (row < NROWS) {
            float* dst = &g_part[z][(size_t)row * DMODEL + n0 + ty * 8];
#pragma unroll
            for (int j = 0; j < 8; j++) dst[j] = acc[i][j];
        }
    }
}

// ---------------- final reduce: out = xn + sum_z partial[z], float4 vectorized ----------------
__global__ void reduce_kernel(float* __restrict__ out) {
    int idx = (blockIdx.x * 256 + threadIdx.x) * 4;   // grid covers exactly 301056 floats
    float4 s = *reinterpret_cast<const float4*>(&g_xn[idx]);
#pragma unroll
    for (int z = 0; z < SPLITK; z++) {
        float4 p = *reinterpret_cast<const float4*>(&g_part[z][idx]);
        s.x += p.x; s.y += p.y; s.z += p.z; s.w += p.w;
    }
    *reinterpret_cast<float4*>(&out[idx]) = s;
}

// ---------------- launch ----------------
extern "C" void kernel_launch(void* const* d_in, const int* in_sizes, int n_in,
                              void* d_out, int out_size) {
    const float* x     = (const float*)d_in[0];
    const float* Wq    = (const float*)d_in[1];
    const float* Wk    = (const float*)d_in[2];
    const float* Wv    = (const float*)d_in[3];
    const float* Wout  = (const float*)d_in[4];
    const float* gamma = (const float*)d_in[5];
    const float* beta  = (const float*)d_in[6];

    float* out   = (float*)d_out;
    // output tuple = (out, probs) flattened: out first (301056), probs after (58982400)
    float* probs = (out_size >= NROWS * DMODEL + NBC * NTOK * NTOK)
                 ? out + NROWS * DMODEL : nullptr;

    ln_kernel<<<NROWS, 128>>>(x, gamma, beta);

    dim3 pgrid(HDIM / 128, (NROWS + 127) / 128, 3);     // 48 x 7 x 3
    proj_gemm<<<pgrid, 256>>>(Wq, Wk, Wv);

    attn_kernel<<<NBC, 256>>>(probs);

    dim3 wgrid(DMODEL / 128, (NROWS + 127) / 128, SPLITK);   // 3 x 7 x 16
    wout_gemm<<<wgrid, 256>>>(Wout);

    reduce_kernel<<<(NROWS * DMODEL) / 1024, 256>>>(out);
}

// round 15
// speedup vs baseline: 1.1480x; 1.0492x over previous
#include <cuda_runtime.h>
#include <cstddef>

#define NTOK   196
#define DMODEL 384
#define NHEADS 16
#define HDIM   6144
#define NBATCH 4
#define NROWS  784          // NBATCH * NTOK
#define NBC    1536         // NBATCH * DMODEL
#define SPLITK 16

// ---------------- scratch (static __device__, no allocation) ----------------
__device__ float g_xn[NROWS * DMODEL];                         // 1.2 MB
// qkv layout: [b][c][h][i]  (per (b,c): 16*196 contiguous floats)
__device__ float g_q[(size_t)NBC * NHEADS * NTOK];             // 19.3 MB
__device__ float g_k[(size_t)NBC * NHEADS * NTOK];
__device__ float g_v[(size_t)NBC * NHEADS * NTOK];
// attn out layout: [row][ c*16 + h ]  (K-permuted for dense 64B writes)
__device__ float g_attn[(size_t)NROWS * HDIM];                 // 19.3 MB
__device__ float g_part[SPLITK][NROWS * DMODEL];               // 19.3 MB

// ---------------- packed f32x2 helpers (sm_100+; ptxas never emits FFMA2 from C++) ----
__device__ __forceinline__ unsigned long long pack2(float lo, float hi) {
    unsigned long long r;
    asm("mov.b64 %0, {%1, %2};" : "=l"(r) : "f"(lo), "f"(hi));
    return r;
}
__device__ __forceinline__ void fma2(unsigned long long& d,
                                     unsigned long long a, unsigned long long b) {
    asm("fma.rn.f32x2 %0, %1, %2, %0;" : "+l"(d) : "l"(a), "l"(b));
}
__device__ __forceinline__ unsigned long long add2(unsigned long long a,
                                                   unsigned long long b) {
    unsigned long long r;
    asm("add.rn.f32x2 %0, %1, %2;" : "=l"(r) : "l"(a), "l"(b));
    return r;
}
__device__ __forceinline__ void unpack2(unsigned long long v, float& lo, float& hi) {
    asm("mov.b64 {%0, %1}, %2;" : "=f"(lo), "=f"(hi) : "l"(v));
}

// ---------------- cp.async helpers ----------------
__device__ __forceinline__ unsigned int smem_u32(const void* p) {
    unsigned int r;
    asm("{ .reg .u64 t; cvta.to.shared.u64 t, %1; cvt.u32.u64 %0, t; }"
        : "=r"(r) : "l"(p));
    return r;
}
__device__ __forceinline__ void cp_async16(unsigned int dst, const void* src) {
    asm volatile("cp.async.cg.shared.global [%0], [%1], 16;\n"
                 :: "r"(dst), "l"(src) : "memory");
}
#define CP_COMMIT() asm volatile("cp.async.commit_group;\n" ::: "memory")
#define CP_WAIT1()  asm volatile("cp.async.wait_group 1;\n" ::: "memory")

// ---------------- LayerNorm ----------------
__global__ void ln_kernel(const float* __restrict__ x,
                          const float* __restrict__ gamma,
                          const float* __restrict__ beta) {
    int row = blockIdx.x;
    int tid = threadIdx.x;                 // 128 threads
    const float* xr = x + (size_t)row * DMODEL;

    float v[3];
    float s = 0.f, s2 = 0.f;
#pragma unroll
    for (int t = 0; t < 3; t++) {
        float val = xr[tid + t * 128];
        v[t] = val;
        s  += val;
        s2 += val * val;
    }
#pragma unroll
    for (int off = 16; off; off >>= 1) {
        s  += __shfl_xor_sync(0xffffffffu, s,  off);
        s2 += __shfl_xor_sync(0xffffffffu, s2, off);
    }
    __shared__ float red[2][4];
    int wid = tid >> 5, lane = tid & 31;
    if (lane == 0) { red[0][wid] = s; red[1][wid] = s2; }
    __syncthreads();
    s  = red[0][0] + red[0][1] + red[0][2] + red[0][3];
    s2 = red[1][0] + red[1][1] + red[1][2] + red[1][3];

    float mu  = s * (1.f / DMODEL);
    float var = s2 * (1.f / DMODEL) - mu * mu;
    float inv = rsqrtf(var + 1e-5f);
#pragma unroll
    for (int t = 0; t < 3; t++) {
        int c = tid + t * 128;
        g_xn[(size_t)row * DMODEL + c] = (v[t] - mu) * inv * gamma[c] + beta[c];
    }
}

// ---------------- Fused projection GEMM: xn(784x384) @ W(384x6144), z selects Wq/Wk/Wv ----
// BM=BN=128, BK=16, 256 threads, 8x8 microtile (rows tx*4..+3 and 64+tx*4..+3 —
// conflict-free 16B-stride LDS), packed f32x2. A: reg double-buffer. B: cp.async 3-stage.
__global__ __launch_bounds__(256, 2) void proj_gemm(const float* __restrict__ Wq,
                                                    const float* __restrict__ Wk,
                                                    const float* __restrict__ Wv) {
    int which = blockIdx.z;
    const float* W = (which == 0) ? Wq : (which == 1) ? Wk : Wv;
    float* outp    = (which == 0) ? g_q : (which == 1) ? g_k : g_v;

    __shared__ float As[2][16][128];
    __shared__ float Bs[3][16][128];

    int n0 = blockIdx.x * 128;
    int m0 = blockIdx.y * 128;
    int tid = threadIdx.x;
    int tx = tid & 15;        // row group
    int ty = tid >> 4;        // col group

    int ar   = tid >> 1;            // 0..127
    int ak   = (tid & 1) * 4;       // 0 or 4 (plus +8 for second half)
    int arow = m0 + ar;

    // B cp.async coords: 2 units of 16B per thread per stage
    int br0  = tid >> 5;            // rows 0..7
    int br1  = br0 + 8;             // rows 8..15
    int bcf  = (tid & 31) * 4;      // float offset 0..124

    unsigned long long acc2[8][4] = {};   // (0.f,0.f) == 0ull
    const int NK = DMODEL / 16;           // 24

    // --- prologue: B stages 0,1 via cp.async; A tile 0 via regs+STS ---
    cp_async16(smem_u32(&Bs[0][br0][bcf]), &W[(size_t)br0 * HDIM + n0 + bcf]);
    cp_async16(smem_u32(&Bs[0][br1][bcf]), &W[(size_t)br1 * HDIM + n0 + bcf]);
    CP_COMMIT();
    cp_async16(smem_u32(&Bs[1][br0][bcf]), &W[(size_t)(16 + br0) * HDIM + n0 + bcf]);
    cp_async16(smem_u32(&Bs[1][br1][bcf]), &W[(size_t)(16 + br1) * HDIM + n0 + bcf]);
    CP_COMMIT();
    {
        float4 a0v, a1v;
        if (arow < NROWS) {
            a0v = *reinterpret_cast<const float4*>(&g_xn[(size_t)arow * DMODEL + ak]);
            a1v = *reinterpret_cast<const float4*>(&g_xn[(size_t)arow * DMODEL + ak + 8]);
        } else { a0v = a1v = make_float4(0.f, 0.f, 0.f, 0.f); }
        As[0][ak + 0][ar] = a0v.x; As[0][ak + 1][ar] = a0v.y;
        As[0][ak + 2][ar] = a0v.z; As[0][ak + 3][ar] = a0v.w;
        As[0][ak + 8][ar] = a1v.x; As[0][ak + 9][ar] = a1v.y;
        As[0][ak + 10][ar] = a1v.z; As[0][ak + 11][ar] = a1v.w;
    }
    CP_WAIT1();            // stage 0 complete
    __syncthreads();

    int buf = 0;
    for (int it = 0; it < NK; ++it) {
        int kt = it * 16;
        float4 a0v, a1v;
        bool more = (it + 1 < NK);
        if (more) {
            if (arow < NROWS) {
                a0v = *reinterpret_cast<const float4*>(&g_xn[(size_t)arow * DMODEL + kt + 16 + ak]);
                a1v = *reinterpret_cast<const float4*>(&g_xn[(size_t)arow * DMODEL + kt + 16 + ak + 8]);
            } else { a0v = a1v = make_float4(0.f, 0.f, 0.f, 0.f); }
        }
        if (it + 2 < NK) {
            int s  = (it + 2) % 3;
            int kb = kt + 32;
            cp_async16(smem_u32(&Bs[s][br0][bcf]), &W[(size_t)(kb + br0) * HDIM + n0 + bcf]);
            cp_async16(smem_u32(&Bs[s][br1][bcf]), &W[(size_t)(kb + br1) * HDIM + n0 + bcf]);
        }
        CP_COMMIT();       // one group per iteration (possibly empty)

        int bs = it % 3;
#pragma unroll
        for (int k = 0; k < 16; k++) {
            // conflict-free A reads: 16B stride across lanes (rows tx*4 and 64+tx*4)
            float4 a0 = *reinterpret_cast<const float4*>(&As[buf][k][tx * 4]);
            float4 a1 = *reinterpret_cast<const float4*>(&As[buf][k][64 + tx * 4]);
            ulonglong2 bq0 = *reinterpret_cast<const ulonglong2*>(&Bs[bs][k][ty * 8]);
            ulonglong2 bq1 = *reinterpret_cast<const ulonglong2*>(&Bs[bs][k][ty * 8 + 4]);
            float a[8] = {a0.x, a0.y, a0.z, a0.w, a1.x, a1.y, a1.z, a1.w};
#pragma unroll
            for (int i = 0; i < 8; i++) {
                unsigned long long ap = pack2(a[i], a[i]);
                fma2(acc2[i][0], ap, bq0.x);
                fma2(acc2[i][1], ap, bq0.y);
                fma2(acc2[i][2], ap, bq1.x);
                fma2(acc2[i][3], ap, bq1.y);
            }
        }
        if (more) {
            int nb = buf ^ 1;
            As[nb][ak + 0][ar] = a0v.x; As[nb][ak + 1][ar] = a0v.y;
            As[nb][ak + 2][ar] = a0v.z; As[nb][ak + 3][ar] = a0v.w;
            As[nb][ak + 8][ar] = a1v.x; As[nb][ak + 9][ar] = a1v.y;
            As[nb][ak + 10][ar] = a1v.z; As[nb][ak + 11][ar] = a1v.w;
            CP_WAIT1();    // next stage complete
            __syncthreads();
            buf = nb;
        }
    }

    // unpack accumulators
    float acc[8][8];
#pragma unroll
    for (int i = 0; i < 8; i++)
#pragma unroll
        for (int jj = 0; jj < 4; jj++)
            unpack2(acc2[i][jj], acc[i][2 * jj], acc[i][2 * jj + 1]);

    // epilogue: col j_glob = n0 + ty*8 + j lies in one h (384 = 3*128 tiles).
    // rows: group g covers m0 + g*64 + tx*4 + (0..3), acc row index = g*4+i.
    // address = ((b*DMODEL + c)*NHEADS + h)*NTOK + i
    int h  = n0 / DMODEL;
    int cb = n0 - h * DMODEL + ty * 8;
#pragma unroll
    for (int g = 0; g < 2; g++) {
        int rb = m0 + g * 64 + tx * 4;
        int bfirst = rb / NTOK;
        int blast  = (rb + 3) / NTOK;
        if (rb + 3 < NROWS && bfirst == blast) {
            int ii0 = rb - bfirst * NTOK;          // multiple of 4 -> float4 aligned
#pragma unroll
            for (int j = 0; j < 8; j++) {
                int c = cb + j;
                float* dst = &outp[((size_t)(bfirst * DMODEL + c) * NHEADS + h) * NTOK + ii0];
                *reinterpret_cast<float4*>(dst) =
                    make_float4(acc[g * 4 + 0][j], acc[g * 4 + 1][j],
                                acc[g * 4 + 2][j], acc[g * 4 + 3][j]);
            }
        } else {
#pragma unroll
            for (int i = 0; i < 4; i++) {
                int row = rb + i;
                if (row < NROWS) {
                    int b  = row / NTOK;
                    int ii = row - b * NTOK;
#pragma unroll
                    for (int j = 0; j < 8; j++) {
                        int c = cb + j;
                        outp[((size_t)(b * DMODEL + c) * NHEADS + h) * NTOK + ii] = acc[g * 4 + i][j];
                    }
                }
            }
        }
    }
}

// ---------------- Channel attention: one block per (b,c), packed f32x2 math ----------------
__global__ __launch_bounds__(256) void attn_kernel(float* __restrict__ probs) {
    int bc = blockIdx.x;                   // b*384 + c
    __shared__ float Qs[NTOK][16];
    __shared__ float Ks[NTOK][20];         // 80B row stride: 16B-aligned, LDS.128 conflict-free
    __shared__ float Vs[NTOK][20];

    int tid = threadIdx.x;
    size_t qb = (size_t)bc * (NTOK * NHEADS);
    // memory layout [h][i]; smem layout [i][h]. Global reads stay contiguous.
    for (int idx = tid; idx < NTOK * NHEADS; idx += 256) {
        int h = idx / NTOK;
        int i = idx - h * NTOK;
        Qs[i][h] = g_q[qb + idx];
        Ks[i][h] = g_k[qb + idx];
        Vs[i][h] = g_v[qb + idx];
    }
    __syncthreads();

    int wid = tid >> 5, lane = tid & 31;
    const float scale = 0.05103103630798288f;   // 1/sqrt(384)

    for (int i = wid; i < NTOK; i += 8) {
        // q pairs: 16 floats = 8 packed operands, loaded directly as 64-bit pairs
        ulonglong2 qq0 = *reinterpret_cast<const ulonglong2*>(&Qs[i][0]);
        ulonglong2 qq1 = *reinterpret_cast<const ulonglong2*>(&Qs[i][4]);
        ulonglong2 qq2 = *reinterpret_cast<const ulonglong2*>(&Qs[i][8]);
        ulonglong2 qq3 = *reinterpret_cast<const ulonglong2*>(&Qs[i][12]);

        float sv[7];
        float m = -1e30f;
#pragma unroll
        for (int t = 0; t < 7; t++) {
            int j = lane + t * 32;
            float s = -1e30f;
            if (j < NTOK) {
                ulonglong2 k0 = *reinterpret_cast<const ulonglong2*>(&Ks[j][0]);
                ulonglong2 k1 = *reinterpret_cast<const ulonglong2*>(&Ks[j][4]);
                ulonglong2 k2 = *reinterpret_cast<const ulonglong2*>(&Ks[j][8]);
                ulonglong2 k3 = *reinterpret_cast<const ulonglong2*>(&Ks[j][12]);
                unsigned long long d2 = 0ull;
                fma2(d2, qq0.x, k0.x); fma2(d2, qq0.y, k0.y);
                fma2(d2, qq1.x, k1.x); fma2(d2, qq1.y, k1.y);
                fma2(d2, qq2.x, k2.x); fma2(d2, qq2.y, k2.y);
                fma2(d2, qq3.x, k3.x); fma2(d2, qq3.y, k3.y);
                float lo, hi;
                unpack2(d2, lo, hi);
                s = (lo + hi) * scale;
            }
            sv[t] = s;
            m = fmaxf(m, s);
        }
#pragma unroll
        for (int off = 16; off; off >>= 1)
            m = fmaxf(m, __shfl_xor_sync(0xffffffffu, m, off));

        float sum = 0.f;
#pragma unroll
        for (int t = 0; t < 7; t++) {
            float e = __expf(sv[t] - m);   // lanes with j>=196 underflow to 0
            sv[t] = e;
            sum += e;
        }
#pragma unroll
        for (int off = 16; off; off >>= 1)
            sum += __shfl_xor_sync(0xffffffffu, sum, off);
        float inv = 1.0f / sum;

        unsigned long long o2[8] = {};          // 16 head accumulators, packed
        size_t prow = ((size_t)bc * NTOK + i) * NTOK;
#pragma unroll
        for (int t = 0; t < 7; t++) {
            int j = lane + t * 32;
            if (j < NTOK) {
                float p = sv[t] * inv;
                if (probs) __stcs(&probs[prow + j], p);   // streaming: never re-read
                unsigned long long pp = pack2(p, p);
                ulonglong2 v0 = *reinterpret_cast<const ulonglong2*>(&Vs[j][0]);
                ulonglong2 v1 = *reinterpret_cast<const ulonglong2*>(&Vs[j][4]);
                ulonglong2 v2 = *reinterpret_cast<const ulonglong2*>(&Vs[j][8]);
                ulonglong2 v3 = *reinterpret_cast<const ulonglong2*>(&Vs[j][12]);
                fma2(o2[0], pp, v0.x); fma2(o2[1], pp, v0.y);
                fma2(o2[2], pp, v1.x); fma2(o2[3], pp, v1.y);
                fma2(o2[4], pp, v2.x); fma2(o2[5], pp, v2.y);
                fma2(o2[6], pp, v3.x); fma2(o2[7], pp, v3.y);
            }
        }
#pragma unroll
        for (int off = 16; off; off >>= 1)
#pragma unroll
            for (int h = 0; h < 8; h++)
                o2[h] = add2(o2[h], __shfl_xor_sync(0xffffffffu, o2[h], off));

        if (lane < 16) {
            float lo, hi;
            unpack2(o2[lane >> 1], lo, hi);
            float val = (lane & 1) ? hi : lo;
            int bb = bc / DMODEL;
            int c  = bc - bb * DMODEL;
            // K-permuted layout: k' = c*16 + h  -> 16 lanes write 64B contiguous
            g_attn[(size_t)(bb * NTOK + i) * HDIM + c * NHEADS + lane] = val;
        }
    }
}

// ---------------- Wout GEMM (split-K=16, BK=16, cp.async B pipeline, packed f32x2) ------
// A = g_attn [row][k'], k' = c*16+h. B rows permuted: orig Wout row = (k'&15)*384 + (k'>>4).
__global__ __launch_bounds__(256, 2) void wout_gemm(const float* __restrict__ Wout) {
    __shared__ float As[2][16][128];
    __shared__ float Bs[3][16][128];

    int n0 = blockIdx.x * 128;            // 0..2
    int m0 = blockIdx.y * 128;            // 0..6
    int z  = blockIdx.z;                  // 0..SPLITK-1
    int kbase = z * (HDIM / SPLITK);      // 384 per chunk

    int tid = threadIdx.x;
    int tx = tid & 15, ty = tid >> 4;
    int ar   = tid >> 1;
    int ak   = (tid & 1) * 4;
    int arow = m0 + ar;

    int br0  = tid >> 5;
    int br1  = br0 + 8;
    int bcf  = (tid & 31) * 4;

    unsigned long long acc2[8][4] = {};
    const int NK = (HDIM / SPLITK) / 16;  // 24

    // --- prologue ---
    {
        int kp0 = kbase + br0, kp1 = kbase + br1;
        int r0 = (kp0 & 15) * DMODEL + (kp0 >> 4);
        int r1 = (kp1 & 15) * DMODEL + (kp1 >> 4);
        cp_async16(smem_u32(&Bs[0][br0][bcf]), &Wout[(size_t)r0 * DMODEL + n0 + bcf]);
        cp_async16(smem_u32(&Bs[0][br1][bcf]), &Wout[(size_t)r1 * DMODEL + n0 + bcf]);
        CP_COMMIT();
        kp0 += 16; kp1 += 16;
        r0 = (kp0 & 15) * DMODEL + (kp0 >> 4);
        r1 = (kp1 & 15) * DMODEL + (kp1 >> 4);
        cp_async16(smem_u32(&Bs[1][br0][bcf]), &Wout[(size_t)r0 * DMODEL + n0 + bcf]);
        cp_async16(smem_u32(&Bs[1][br1][bcf]), &Wout[(size_t)r1 * DMODEL + n0 + bcf]);
        CP_COMMIT();
    }
    {
        float4 a0v, a1v;
        if (arow < NROWS) {
            a0v = *reinterpret_cast<const float4*>(&g_attn[(size_t)arow * HDIM + kbase + ak]);
            a1v = *reinterpret_cast<const float4*>(&g_attn[(size_t)arow * HDIM + kbase + ak + 8]);
        } else { a0v = a1v = make_float4(0.f, 0.f, 0.f, 0.f); }
        As[0][ak + 0][ar] = a0v.x; As[0][ak + 1][ar] = a0v.y;
        As[0][ak + 2][ar] = a0v.z; As[0][ak + 3][ar] = a0v.w;
        As[0][ak + 8][ar] = a1v.x; As[0][ak + 9][ar] = a1v.y;
        As[0][ak + 10][ar] = a1v.z; As[0][ak + 11][ar] = a1v.w;
    }
    CP_WAIT1();
    __syncthreads();

    int buf = 0;
    for (int it = 0; it < NK; ++it) {
        int kt = it * 16;
        float4 a0v, a1v;
        bool more = (it + 1 < NK);
        if (more) {
            if (arow < NROWS) {
                a0v = *reinterpret_cast<const float4*>(&g_attn[(size_t)arow * HDIM + kbase + kt + 16 + ak]);
                a1v = *reinterpret_cast<const float4*>(&g_attn[(size_t)arow * HDIM + kbase + kt + 16 + ak + 8]);
            } else { a0v = a1v = make_float4(0.f, 0.f, 0.f, 0.f); }
        }
        if (it + 2 < NK) {
            int s  = (it + 2) % 3;
            int kp0 = kbase + kt + 32 + br0;
            int kp1 = kbase + kt + 32 + br1;
            int r0 = (kp0 & 15) * DMODEL + (kp0 >> 4);
            int r1 = (kp1 & 15) * DMODEL + (kp1 >> 4);
            cp_async16(smem_u32(&Bs[s][br0][bcf]), &Wout[(size_t)r0 * DMODEL + n0 + bcf]);
            cp_async16(smem_u32(&Bs[s][br1][bcf]), &Wout[(size_t)r1 * DMODEL + n0 + bcf]);
        }
        CP_COMMIT();

        int bs = it % 3;
#pragma unroll
        for (int k = 0; k < 16; k++) {
            // conflict-free A reads: 16B stride across lanes
            float4 a0 = *reinterpret_cast<const float4*>(&As[buf][k][tx * 4]);
            float4 a1 = *reinterpret_cast<const float4*>(&As[buf][k][64 + tx * 4]);
            ulonglong2 bq0 = *reinterpret_cast<const ulonglong2*>(&Bs[bs][k][ty * 8]);
            ulonglong2 bq1 = *reinterpret_cast<const ulonglong2*>(&Bs[bs][k][ty * 8 + 4]);
            float a[8] = {a0.x, a0.y, a0.z, a0.w, a1.x, a1.y, a1.z, a1.w};
#pragma unroll
            for (int i = 0; i < 8; i++) {
                unsigned long long ap = pack2(a[i], a[i]);
                fma2(acc2[i][0], ap, bq0.x);
                fma2(acc2[i][1], ap, bq0.y);
                fma2(acc2[i][2], ap, bq1.x);
                fma2(acc2[i][3], ap, bq1.y);
            }
        }
        if (more) {
            int nb = buf ^ 1;
            As[nb][ak + 0][ar] = a0v.x; As[nb][ak + 1][ar] = a0v.y;
            As[nb][ak + 2][ar] = a0v.z; As[nb][ak + 3][ar] = a0v.w;
            As[nb][ak + 8][ar] = a1v.x; As[nb][ak + 9][ar] = a1v.y;
            As[nb][ak + 10][ar] = a1v.z; As[nb][ak + 11][ar] = a1v.w;
            CP_WAIT1();
            __syncthreads();
            buf = nb;
        }
    }

    float acc[8][8];
#pragma unroll
    for (int i = 0; i < 8; i++)
#pragma unroll
        for (int jj = 0; jj < 4; jj++)
            unpack2(acc2[i][jj], acc[i][2 * jj], acc[i][2 * jj + 1]);

    // rows: group g covers m0 + g*64 + tx*4 + (0..3)
#pragma unroll
    for (int g = 0; g < 2; g++) {
#pragma unroll
        for (int i = 0; i < 4; i++) {
            int row = m0 + g * 64 + tx * 4 + i;
            if (row < NROWS) {
                float* dst = &g_part[z][(size_t)row * DMODEL + n0 + ty * 8];
#pragma unroll
                for (int j = 0; j < 8; j++) dst[j] = acc[g * 4 + i][j];
            }
        }
    }
}

// ---------------- final reduce: out = xn + sum_z partial[z], float4 vectorized ----------------
__global__ void reduce_kernel(float* __restrict__ out) {
    int idx = (blockIdx.x * 256 + threadIdx.x) * 4;   // grid covers exactly 301056 floats
    float4 s = *reinterpret_cast<const float4*>(&g_xn[idx]);
#pragma unroll
    for (int z = 0; z < SPLITK; z++) {
        float4 p = *reinterpret_cast<const float4*>(&g_part[z][idx]);
        s.x += p.x; s.y += p.y; s.z += p.z; s.w += p.w;
    }
    *reinterpret_cast<float4*>(&out[idx]) = s;
}

// ---------------- launch ----------------
extern "C" void kernel_launch(void* const* d_in, const int* in_sizes, int n_in,
                              void* d_out, int out_size) {
    const float* x     = (const float*)d_in[0];
    const float* Wq    = (const float*)d_in[1];
    const float* Wk    = (const float*)d_in[2];
    const float* Wv    = (const float*)d_in[3];
    const float* Wout  = (const float*)d_in[4];
    const float* gamma = (const float*)d_in[5];
    const float* beta  = (const float*)d_in[6];

    float* out   = (float*)d_out;
    // output tuple = (out, probs) flattened: out first (301056), probs after (58982400)
    float* probs = (out_size >= NROWS * DMODEL + NBC * NTOK * NTOK)
                 ? out + NROWS * DMODEL : nullptr;

    ln_kernel<<<NROWS, 128>>>(x, gamma, beta);

    dim3 pgrid(HDIM / 128, (NROWS + 127) / 128, 3);     // 48 x 7 x 3
    proj_gemm<<<pgrid, 256>>>(Wq, Wk, Wv);

    attn_kernel<<<NBC, 256>>>(probs);

    dim3 wgrid(DMODEL / 128, (NROWS + 127) / 128, SPLITK);   // 3 x 7 x 16
    wout_gemm<<<wgrid, 256>>>(Wout);

    reduce_kernel<<<(NROWS * DMODEL) / 1024, 256>>>(out);
}